// round 1
// baseline (speedup 1.0000x reference)
#include <cuda_runtime.h>
#include <cstdint>

#define BATCH 16
#define SEQ   2048
#define DIM   128

// padded row stride (in 32-bit words) for shared tiles
#define LDT 132

__device__ __forceinline__ uint32_t f2tf(float x) {
    uint32_t u;
    asm("cvt.rna.tf32.f32 %0, %1;" : "=r"(u) : "f"(x));
    return u;
}

__device__ __forceinline__ void mma_tf32(float acc[4], const uint32_t a[4], const uint32_t b[2]) {
    asm volatile(
        "mma.sync.aligned.m16n8k8.row.col.f32.tf32.tf32.f32 "
        "{%0,%1,%2,%3}, {%4,%5,%6,%7}, {%8,%9}, {%0,%1,%2,%3};"
        : "+f"(acc[0]), "+f"(acc[1]), "+f"(acc[2]), "+f"(acc[3])
        : "r"(a[0]), "r"(a[1]), "r"(a[2]), "r"(a[3]), "r"(b[0]), "r"(b[1]));
}

// ---------------------------------------------------------------------------
// Kernel 1: raw scaled scores.  attn[b,i,j] = scale * sum_d Q[b,i,d]*K[b,j,d]
// grid (S/128 n-tiles, S/128 m-tiles, B), 256 threads.
// ---------------------------------------------------------------------------
extern __shared__ uint32_t smem_u[];

__global__ __launch_bounds__(256, 1)
void k1_scores(const float* __restrict__ Q, const float* __restrict__ K,
               float* __restrict__ attn)
{
    uint32_t* Qs = smem_u;              // [128][LDT] tf32 bits
    uint32_t* Ks = smem_u + 128 * LDT;  // [128][LDT]

    const int tid = threadIdx.x;
    const int bx = blockIdx.x;   // n tile (K rows)
    const int by = blockIdx.y;   // m tile (Q rows)
    const int bz = blockIdx.z;   // batch

    const float* Qg = Q + ((size_t)bz * SEQ + (size_t)by * 128) * DIM;
    const float* Kg = K + ((size_t)bz * SEQ + (size_t)bx * 128) * DIM;

    // fill tiles (tf32-rounded)
#pragma unroll
    for (int i = 0; i < 16; i++) {
        int f = tid + 256 * i;          // float4 index, 4096 total
        int row = f >> 5;
        int c4 = (f & 31) * 4;
        float4 q4 = *(const float4*)(Qg + row * DIM + c4);
        float4 k4 = *(const float4*)(Kg + row * DIM + c4);
        uint32_t* pq = &Qs[row * LDT + c4];
        pq[0] = f2tf(q4.x); pq[1] = f2tf(q4.y); pq[2] = f2tf(q4.z); pq[3] = f2tf(q4.w);
        uint32_t* pk = &Ks[row * LDT + c4];
        pk[0] = f2tf(k4.x); pk[1] = f2tf(k4.y); pk[2] = f2tf(k4.z); pk[3] = f2tf(k4.w);
    }
    __syncthreads();

    const int w    = tid >> 5;
    const int lane = tid & 31;
    const int g    = lane >> 2;   // group id (0..7)
    const int t    = lane & 3;    // thread in group (0..3)
    const int wm   = w & 1;       // 2 warps along M (64 rows each)
    const int wn   = w >> 1;      // 4 warps along N (32 cols each)

    float acc[4][4][4];
#pragma unroll
    for (int mt = 0; mt < 4; mt++)
#pragma unroll
        for (int nt = 0; nt < 4; nt++)
#pragma unroll
            for (int r = 0; r < 4; r++) acc[mt][nt][r] = 0.f;

#pragma unroll
    for (int kk = 0; kk < 16; kk++) {
        const int k0 = kk * 8;
        uint32_t a[4][4], bf[4][2];
#pragma unroll
        for (int mt = 0; mt < 4; mt++) {
            int r = wm * 64 + mt * 16 + g;
            a[mt][0] = Qs[r * LDT + k0 + t];
            a[mt][1] = Qs[(r + 8) * LDT + k0 + t];
            a[mt][2] = Qs[r * LDT + k0 + t + 4];
            a[mt][3] = Qs[(r + 8) * LDT + k0 + t + 4];
        }
#pragma unroll
        for (int nt = 0; nt < 4; nt++) {
            int c = wn * 32 + nt * 8 + g;
            bf[nt][0] = Ks[c * LDT + k0 + t];
            bf[nt][1] = Ks[c * LDT + k0 + t + 4];
        }
#pragma unroll
        for (int mt = 0; mt < 4; mt++)
#pragma unroll
            for (int nt = 0; nt < 4; nt++)
                mma_tf32(acc[mt][nt], a[mt], bf[nt]);
    }

    const float scale = 0.08838834764831845f;  // 1/sqrt(128)
    float* Cg = attn + ((size_t)bz * SEQ + (size_t)by * 128) * SEQ + (size_t)bx * 128;
#pragma unroll
    for (int mt = 0; mt < 4; mt++) {
        int r = wm * 64 + mt * 16 + g;
#pragma unroll
        for (int nt = 0; nt < 4; nt++) {
            int c = wn * 32 + nt * 8 + 2 * t;
            float2 v0 = make_float2(acc[mt][nt][0] * scale, acc[mt][nt][1] * scale);
            float2 v1 = make_float2(acc[mt][nt][2] * scale, acc[mt][nt][3] * scale);
            *(float2*)(Cg + (size_t)r * SEQ + c)       = v0;
            *(float2*)(Cg + (size_t)(r + 8) * SEQ + c) = v1;
        }
    }
}

// ---------------------------------------------------------------------------
// Kernel 2: softmax (in place on attn) + out = P @ V
// grid (S/128 m-tiles, B), 256 threads.
// ---------------------------------------------------------------------------
__global__ __launch_bounds__(256, 1)
void k2_softmax_pv(const float* __restrict__ V, float* __restrict__ attn,
                   float* __restrict__ out)
{
    uint32_t* Ps = smem_u;              // [128][LDT] tf32 bits of P tile
    uint32_t* Vs = smem_u + 128 * LDT;  // [128][LDT] tf32 bits of V tile
    float* sm_m  = (float*)(smem_u + 2 * 128 * LDT);
    float* sm_rl = sm_m + 128;

    const int tid = threadIdx.x;
    const int by = blockIdx.x;   // q tile
    const int bz = blockIdx.y;   // batch

    float* Arow = attn + ((size_t)bz * SEQ + (size_t)by * 128) * SEQ;

    const int w    = tid >> 5;
    const int lane = tid & 31;

    // ---- Phase A: per-row max and 1/sum(exp) over 2048 raw scores ----
    for (int r = 0; r < 16; r++) {
        int row = w * 16 + r;
        const float4* src = (const float4*)(Arow + (size_t)row * SEQ);
        float mx = -3.4e38f;
#pragma unroll
        for (int j = 0; j < 16; j++) {
            float4 v = src[lane + (j << 5)];
            mx = fmaxf(mx, fmaxf(fmaxf(v.x, v.y), fmaxf(v.z, v.w)));
        }
#pragma unroll
        for (int o = 16; o > 0; o >>= 1)
            mx = fmaxf(mx, __shfl_xor_sync(0xFFFFFFFFu, mx, o));

        float sum = 0.f;
#pragma unroll
        for (int j = 0; j < 16; j++) {
            float4 v = src[lane + (j << 5)];
            sum += __expf(v.x - mx) + __expf(v.y - mx) + __expf(v.z - mx) + __expf(v.w - mx);
        }
#pragma unroll
        for (int o = 16; o > 0; o >>= 1)
            sum += __shfl_xor_sync(0xFFFFFFFFu, sum, o);

        if (lane == 0) { sm_m[row] = mx; sm_rl[row] = 1.f / sum; }
    }
    __syncthreads();

    const int g  = lane >> 2;
    const int t  = lane & 3;
    const int wm = w & 1;
    const int wn = w >> 1;

    float acc[4][4][4];
#pragma unroll
    for (int mt = 0; mt < 4; mt++)
#pragma unroll
        for (int nt = 0; nt < 4; nt++)
#pragma unroll
            for (int r = 0; r < 4; r++) acc[mt][nt][r] = 0.f;

    // ---- Phase B: loop over 16 k-tiles of 128 keys ----
    for (int kt = 0; kt < 16; kt++) {
        // P tile: read raw scores, normalize, write back (full fp32),
        // and stage tf32 bits into smem.
#pragma unroll
        for (int i = 0; i < 16; i++) {
            int f = tid + 256 * i;
            int row = f >> 5;
            int c4 = (f & 31) * 4;
            float* addr = Arow + (size_t)row * SEQ + kt * 128 + c4;
            float4 s = *(const float4*)addr;
            float m = sm_m[row], rl = sm_rl[row];
            float4 p;
            p.x = __expf(s.x - m) * rl;
            p.y = __expf(s.y - m) * rl;
            p.z = __expf(s.z - m) * rl;
            p.w = __expf(s.w - m) * rl;
            *(float4*)addr = p;
            uint32_t* pp = &Ps[row * LDT + c4];
            pp[0] = f2tf(p.x); pp[1] = f2tf(p.y); pp[2] = f2tf(p.z); pp[3] = f2tf(p.w);
        }
        // V tile (row-major, tf32)
        const float* Vg = V + ((size_t)bz * SEQ + (size_t)kt * 128) * DIM;
#pragma unroll
        for (int i = 0; i < 16; i++) {
            int f = tid + 256 * i;
            int row = f >> 5;
            int c4 = (f & 31) * 4;
            float4 v = *(const float4*)(Vg + row * DIM + c4);
            uint32_t* pv = &Vs[row * LDT + c4];
            pv[0] = f2tf(v.x); pv[1] = f2tf(v.y); pv[2] = f2tf(v.z); pv[3] = f2tf(v.w);
        }
        __syncthreads();

#pragma unroll
        for (int kk = 0; kk < 16; kk++) {
            const int k0 = kk * 8;
            uint32_t a[4][4], bf[4][2];
#pragma unroll
            for (int mt = 0; mt < 4; mt++) {
                int r = wm * 64 + mt * 16 + g;
                a[mt][0] = Ps[r * LDT + k0 + t];
                a[mt][1] = Ps[(r + 8) * LDT + k0 + t];
                a[mt][2] = Ps[r * LDT + k0 + t + 4];
                a[mt][3] = Ps[(r + 8) * LDT + k0 + t + 4];
            }
#pragma unroll
            for (int nt = 0; nt < 4; nt++) {
                int c = wn * 32 + nt * 8 + g;
                bf[nt][0] = Vs[(k0 + t) * LDT + c];
                bf[nt][1] = Vs[(k0 + t + 4) * LDT + c];
            }
#pragma unroll
            for (int mt = 0; mt < 4; mt++)
#pragma unroll
                for (int nt = 0; nt < 4; nt++)
                    mma_tf32(acc[mt][nt], a[mt], bf[nt]);
        }
        __syncthreads();
    }

    // epilogue: out[b, i, d]
    float* Og = out + ((size_t)bz * SEQ + (size_t)by * 128) * DIM;
#pragma unroll
    for (int mt = 0; mt < 4; mt++) {
        int r = wm * 64 + mt * 16 + g;
#pragma unroll
        for (int nt = 0; nt < 4; nt++) {
            int c = wn * 32 + nt * 8 + 2 * t;
            *(float2*)(Og + (size_t)r * DIM + c)       = make_float2(acc[mt][nt][0], acc[mt][nt][1]);
            *(float2*)(Og + (size_t)(r + 8) * DIM + c) = make_float2(acc[mt][nt][2], acc[mt][nt][3]);
        }
    }
}

// ---------------------------------------------------------------------------
extern "C" void kernel_launch(void* const* d_in, const int* in_sizes, int n_in,
                              void* d_out, int out_size)
{
    const float* Q = (const float*)d_in[0];
    const float* K = (const float*)d_in[1];
    const float* V = (const float*)d_in[2];
    float* out  = (float*)d_out;                                  // [B,S,D]
    float* attn = out + (size_t)BATCH * SEQ * DIM;                // [B,S,S]

    const int smem1 = 2 * 128 * LDT * 4;              // 135168 B
    const int smem2 = 2 * 128 * LDT * 4 + 2 * 128 * 4; // +m/rl

    cudaFuncSetAttribute(k1_scores, cudaFuncAttributeMaxDynamicSharedMemorySize, smem1);
    cudaFuncSetAttribute(k2_softmax_pv, cudaFuncAttributeMaxDynamicSharedMemorySize, smem2);

    dim3 g1(SEQ / 128, SEQ / 128, BATCH);
    k1_scores<<<g1, 256, smem1>>>(Q, K, attn);

    dim3 g2(SEQ / 128, BATCH);
    k2_softmax_pv<<<g2, 256, smem2>>>(V, attn, out);
}

// round 2
// speedup vs baseline: 1.1891x; 1.1891x over previous
#include <cuda_runtime.h>
#include <cstdint>

#define BATCH 16
#define SEQ   2048
#define DIM   128
#define LDT   132   // padded row stride (words)

// partial softmax stats: [B][32 row-tiles][16 k-tiles][2 planes][64 rows]
__device__ float g_stats[BATCH * 32 * 16 * 2 * 64];

__device__ __forceinline__ uint32_t f2tf(float x) {
    uint32_t u;
    asm("cvt.rna.tf32.f32 %0, %1;" : "=r"(u) : "f"(x));
    return u;
}

__device__ __forceinline__ void mma_tf32(float acc[4], const uint32_t a[4], const uint32_t b[2]) {
    asm volatile(
        "mma.sync.aligned.m16n8k8.row.col.f32.tf32.tf32.f32 "
        "{%0,%1,%2,%3}, {%4,%5,%6,%7}, {%8,%9}, {%0,%1,%2,%3};"
        : "+f"(acc[0]), "+f"(acc[1]), "+f"(acc[2]), "+f"(acc[3])
        : "r"(a[0]), "r"(a[1]), "r"(a[2]), "r"(a[3]), "r"(b[0]), "r"(b[1]));
}

extern __shared__ uint32_t smem_u[];

// ---------------------------------------------------------------------------
// Kernel 1: scaled scores for a 64(q) x 128(k) tile + per-(row,ktile) partial
// softmax stats (m_t, l_t).  grid (16 kt, 32 rt, B), 256 threads, 2 CTA/SM.
// ---------------------------------------------------------------------------
__global__ __launch_bounds__(256, 2)
void k1_scores(const float* __restrict__ Q, const float* __restrict__ K,
               float* __restrict__ attn)
{
    uint32_t* Qs = smem_u;             // [64][LDT]
    uint32_t* Ks = smem_u + 64 * LDT;  // [128][LDT]
    float* sm_max = (float*)(smem_u + (64 + 128) * LDT);  // [4][64]
    float* sm_sum = sm_max + 4 * 64;                       // [4][64]

    const int tid = threadIdx.x;
    const int kt = blockIdx.x;
    const int rt = blockIdx.y;
    const int b  = blockIdx.z;

    const float* Qg = Q + ((size_t)b * SEQ + (size_t)rt * 64) * DIM;
    const float* Kg = K + ((size_t)b * SEQ + (size_t)kt * 128) * DIM;

#pragma unroll
    for (int i = 0; i < 8; i++) {                 // Q tile: 64x128 = 2048 float4
        int f = tid + 256 * i;
        int row = f >> 5;
        int c4 = (f & 31) * 4;
        float4 q4 = *(const float4*)(Qg + row * DIM + c4);
        uint32_t* pq = &Qs[row * LDT + c4];
        pq[0] = f2tf(q4.x); pq[1] = f2tf(q4.y); pq[2] = f2tf(q4.z); pq[3] = f2tf(q4.w);
    }
#pragma unroll
    for (int i = 0; i < 16; i++) {                // K tile: 128x128 = 4096 float4
        int f = tid + 256 * i;
        int row = f >> 5;
        int c4 = (f & 31) * 4;
        float4 k4 = *(const float4*)(Kg + row * DIM + c4);
        uint32_t* pk = &Ks[row * LDT + c4];
        pk[0] = f2tf(k4.x); pk[1] = f2tf(k4.y); pk[2] = f2tf(k4.z); pk[3] = f2tf(k4.w);
    }
    __syncthreads();

    const int w = tid >> 5, lane = tid & 31;
    const int g = lane >> 2, t = lane & 3;
    const int wm = w & 1;        // 2 warps x 32 rows
    const int wn = w >> 1;       // 4 warps x 32 cols

    float acc[2][4][4];
#pragma unroll
    for (int mt = 0; mt < 2; mt++)
#pragma unroll
        for (int nt = 0; nt < 4; nt++)
#pragma unroll
            for (int r = 0; r < 4; r++) acc[mt][nt][r] = 0.f;

#pragma unroll
    for (int kk = 0; kk < 16; kk++) {
        const int k0 = kk * 8;
        uint32_t a[2][4], bf[4][2];
#pragma unroll
        for (int mt = 0; mt < 2; mt++) {
            int r = wm * 32 + mt * 16 + g;
            a[mt][0] = Qs[r * LDT + k0 + t];
            a[mt][1] = Qs[(r + 8) * LDT + k0 + t];
            a[mt][2] = Qs[r * LDT + k0 + t + 4];
            a[mt][3] = Qs[(r + 8) * LDT + k0 + t + 4];
        }
#pragma unroll
        for (int nt = 0; nt < 4; nt++) {
            int c = wn * 32 + nt * 8 + g;
            bf[nt][0] = Ks[c * LDT + k0 + t];
            bf[nt][1] = Ks[c * LDT + k0 + t + 4];
        }
#pragma unroll
        for (int mt = 0; mt < 2; mt++)
#pragma unroll
            for (int nt = 0; nt < 4; nt++)
                mma_tf32(acc[mt][nt], a[mt], bf[nt]);
    }

    const float scale = 0.08838834764831845f;  // 1/sqrt(128)
#pragma unroll
    for (int mt = 0; mt < 2; mt++)
#pragma unroll
        for (int nt = 0; nt < 4; nt++)
#pragma unroll
            for (int r = 0; r < 4; r++) acc[mt][nt][r] *= scale;

    // ---- per-row max over this warp's 32 cols, then across the 4 wn warps ----
#pragma unroll
    for (int mt = 0; mt < 2; mt++)
#pragma unroll
        for (int rr = 0; rr < 2; rr++) {
            float mx = -3.4e38f;
#pragma unroll
            for (int nt = 0; nt < 4; nt++)
                mx = fmaxf(mx, fmaxf(acc[mt][nt][2 * rr], acc[mt][nt][2 * rr + 1]));
            mx = fmaxf(mx, __shfl_xor_sync(0xFFFFFFFFu, mx, 1));
            mx = fmaxf(mx, __shfl_xor_sync(0xFFFFFFFFu, mx, 2));
            if (t == 0) sm_max[wn * 64 + wm * 32 + mt * 16 + rr * 8 + g] = mx;
        }
    __syncthreads();

#pragma unroll
    for (int mt = 0; mt < 2; mt++)
#pragma unroll
        for (int rr = 0; rr < 2; rr++) {
            int row = wm * 32 + mt * 16 + rr * 8 + g;
            float m = fmaxf(fmaxf(sm_max[row], sm_max[64 + row]),
                            fmaxf(sm_max[128 + row], sm_max[192 + row]));
            float s = 0.f;
#pragma unroll
            for (int nt = 0; nt < 4; nt++)
                s += __expf(acc[mt][nt][2 * rr] - m) + __expf(acc[mt][nt][2 * rr + 1] - m);
            s += __shfl_xor_sync(0xFFFFFFFFu, s, 1);
            s += __shfl_xor_sync(0xFFFFFFFFu, s, 2);
            if (t == 0) sm_sum[wn * 64 + row] = s;
        }
    __syncthreads();

    if (tid < 64) {
        int row = tid;
        float m = fmaxf(fmaxf(sm_max[row], sm_max[64 + row]),
                        fmaxf(sm_max[128 + row], sm_max[192 + row]));
        float l = sm_sum[row] + sm_sum[64 + row] + sm_sum[128 + row] + sm_sum[192 + row];
        size_t base = ((((size_t)b * 32 + rt) * 16 + kt) * 2) * 64;
        g_stats[base + row]      = m;
        g_stats[base + 64 + row] = l;
    }

    // ---- store raw scaled scores ----
    float* Cg = attn + ((size_t)b * SEQ + (size_t)rt * 64) * SEQ + (size_t)kt * 128;
#pragma unroll
    for (int mt = 0; mt < 2; mt++) {
        int r = wm * 32 + mt * 16 + g;
#pragma unroll
        for (int nt = 0; nt < 4; nt++) {
            int c = wn * 32 + nt * 8 + 2 * t;
            *(float2*)(Cg + (size_t)r * SEQ + c)       = make_float2(acc[mt][nt][0], acc[mt][nt][1]);
            *(float2*)(Cg + (size_t)(r + 8) * SEQ + c) = make_float2(acc[mt][nt][2], acc[mt][nt][3]);
        }
    }
}

// ---------------------------------------------------------------------------
// Kernel 2: combine stats, normalize scores in place, out = P @ V.
// grid (32 rt, B), 256 threads, 2 CTA/SM.
// ---------------------------------------------------------------------------
__global__ __launch_bounds__(256, 2)
void k2_softmax_pv(const float* __restrict__ V, float* __restrict__ attn,
                   float* __restrict__ out)
{
    uint32_t* Ps = smem_u;             // [64][LDT]
    uint32_t* Vs = smem_u + 64 * LDT;  // [128][LDT]
    float* sm_m  = (float*)(smem_u + (64 + 128) * LDT);
    float* sm_rl = sm_m + 64;

    const int tid = threadIdx.x;
    const int rt = blockIdx.x;
    const int b  = blockIdx.y;

    float* Arow = attn + ((size_t)b * SEQ + (size_t)rt * 64) * SEQ;

    // ---- Phase A: combine 16 partial (m,l) per row ----
    if (tid < 64) {
        int row = tid;
        size_t base = (((size_t)b * 32 + rt) * 16) * 2 * 64;
        float m = -3.4e38f;
        float mt_v[16], lt_v[16];
#pragma unroll
        for (int kt = 0; kt < 16; kt++) {
            mt_v[kt] = g_stats[base + (size_t)kt * 128 + row];
            lt_v[kt] = g_stats[base + (size_t)kt * 128 + 64 + row];
            m = fmaxf(m, mt_v[kt]);
        }
        float l = 0.f;
#pragma unroll
        for (int kt = 0; kt < 16; kt++)
            l += lt_v[kt] * __expf(mt_v[kt] - m);
        sm_m[row]  = m;
        sm_rl[row] = 1.f / l;
    }
    __syncthreads();

    const int w = tid >> 5, lane = tid & 31;
    const int g = lane >> 2, t = lane & 3;
    const int wm = w & 1;
    const int wn = w >> 1;

    float acc[2][4][4];
#pragma unroll
    for (int mt = 0; mt < 2; mt++)
#pragma unroll
        for (int nt = 0; nt < 4; nt++)
#pragma unroll
            for (int r = 0; r < 4; r++) acc[mt][nt][r] = 0.f;

    for (int kt = 0; kt < 16; kt++) {
        // P tile: read raw scores, normalize, write back fp32, stage tf32.
#pragma unroll
        for (int i = 0; i < 8; i++) {
            int f = tid + 256 * i;
            int row = f >> 5;
            int c4 = (f & 31) * 4;
            float* addr = Arow + (size_t)row * SEQ + kt * 128 + c4;
            float4 s = *(const float4*)addr;
            float m = sm_m[row], rl = sm_rl[row];
            float4 p;
            p.x = __expf(s.x - m) * rl;
            p.y = __expf(s.y - m) * rl;
            p.z = __expf(s.z - m) * rl;
            p.w = __expf(s.w - m) * rl;
            *(float4*)addr = p;
            uint32_t* pp = &Ps[row * LDT + c4];
            pp[0] = f2tf(p.x); pp[1] = f2tf(p.y); pp[2] = f2tf(p.z); pp[3] = f2tf(p.w);
        }
        // V tile (row-major)
        const float* Vg = V + ((size_t)b * SEQ + (size_t)kt * 128) * DIM;
#pragma unroll
        for (int i = 0; i < 16; i++) {
            int f = tid + 256 * i;
            int row = f >> 5;
            int c4 = (f & 31) * 4;
            float4 v = *(const float4*)(Vg + row * DIM + c4);
            uint32_t* pv = &Vs[row * LDT + c4];
            pv[0] = f2tf(v.x); pv[1] = f2tf(v.y); pv[2] = f2tf(v.z); pv[3] = f2tf(v.w);
        }
        __syncthreads();

#pragma unroll
        for (int kk = 0; kk < 16; kk++) {
            const int k0 = kk * 8;
            uint32_t a[2][4], bf[4][2];
#pragma unroll
            for (int mt = 0; mt < 2; mt++) {
                int r = wm * 32 + mt * 16 + g;
                a[mt][0] = Ps[r * LDT + k0 + t];
                a[mt][1] = Ps[(r + 8) * LDT + k0 + t];
                a[mt][2] = Ps[r * LDT + k0 + t + 4];
                a[mt][3] = Ps[(r + 8) * LDT + k0 + t + 4];
            }
#pragma unroll
            for (int nt = 0; nt < 4; nt++) {
                int c = wn * 32 + nt * 8 + g;
                bf[nt][0] = Vs[(k0 + t) * LDT + c];
                bf[nt][1] = Vs[(k0 + t + 4) * LDT + c];
            }
#pragma unroll
            for (int mt = 0; mt < 2; mt++)
#pragma unroll
                for (int nt = 0; nt < 4; nt++)
                    mma_tf32(acc[mt][nt], a[mt], bf[nt]);
        }
        __syncthreads();
    }

    float* Og = out + ((size_t)b * SEQ + (size_t)rt * 64) * DIM;
#pragma unroll
    for (int mt = 0; mt < 2; mt++) {
        int r = wm * 32 + mt * 16 + g;
#pragma unroll
        for (int nt = 0; nt < 4; nt++) {
            int c = wn * 32 + nt * 8 + 2 * t;
            *(float2*)(Og + (size_t)r * DIM + c)       = make_float2(acc[mt][nt][0], acc[mt][nt][1]);
            *(float2*)(Og + (size_t)(r + 8) * DIM + c) = make_float2(acc[mt][nt][2], acc[mt][nt][3]);
        }
    }
}

// ---------------------------------------------------------------------------
extern "C" void kernel_launch(void* const* d_in, const int* in_sizes, int n_in,
                              void* d_out, int out_size)
{
    const float* Q = (const float*)d_in[0];
    const float* K = (const float*)d_in[1];
    const float* V = (const float*)d_in[2];
    float* out  = (float*)d_out;
    float* attn = out + (size_t)BATCH * SEQ * DIM;

    const int smem1 = (64 + 128) * LDT * 4 + 8 * 64 * 4;   // tiles + red buffers
    const int smem2 = (64 + 128) * LDT * 4 + 2 * 64 * 4;

    cudaFuncSetAttribute(k1_scores, cudaFuncAttributeMaxDynamicSharedMemorySize, smem1);
    cudaFuncSetAttribute(k2_softmax_pv, cudaFuncAttributeMaxDynamicSharedMemorySize, smem2);

    dim3 g1(SEQ / 128, SEQ / 64, BATCH);
    k1_scores<<<g1, 256, smem1>>>(Q, K, attn);

    dim3 g2(SEQ / 64, BATCH);
    k2_softmax_pv<<<g2, 256, smem2>>>(V, attn, out);
}